// round 1
// baseline (speedup 1.0000x reference)
#include <cuda_runtime.h>
#include <cuda_fp16.h>
#include <mma.h>

#define TOKENS (8*2048)
#define EDIM 512

// Scratch (no allocations allowed): permuted attention output in fp16, W in fp16.
__device__ __half g_y[(size_t)TOKENS * EDIM];   // 16 MB
__device__ __half g_W[EDIM * EDIM];             // 512 KB

// ---------------------------------------------------------------------------
// K1: convert W_combine (512x512 f32, row-major [out][in]) to fp16
// ---------------------------------------------------------------------------
__global__ void convert_w_kernel(const float* __restrict__ W) {
    int i = blockIdx.x * 256 + threadIdx.x;   // 262144 elements, grid=1024
    g_W[i] = __float2half(W[i]);
}

// ---------------------------------------------------------------------------
// K2: per-token quantum attention.
// One warp per token. proj[64][8] in smem. Streaming softmax (scores bounded
// by sqrt(8), so no max subtraction needed). Each lane owns heads (lane) and
// (lane+32). Epilogue scatters into the torch-reshape-permuted layout:
//   y[b, h*32 + s/64, (s%64)*8 + d] = attn[b,s,h,d]
// ---------------------------------------------------------------------------
__global__ __launch_bounds__(256) void attn_kernel(const float* __restrict__ x,
                                                   const float* __restrict__ theta) {
    __shared__ float sproj[8][512];
    const int warp = threadIdx.x >> 5;
    const int lane = threadIdx.x & 31;
    const int token = blockIdx.x * 8 + warp;          // [0, 16384)
    const float* xt = x + (size_t)token * EDIM;

    // idx = lane + 32*i  ->  idx & 7 == lane & 7 (constant per lane)
    const float tv = __ldg(&theta[lane & 7]);
    #pragma unroll
    for (int i = 0; i < 16; i++) {
        int idx = lane + 32 * i;
        sproj[warp][idx] = __cosf(xt[idx] + tv);      // conflict-free (bank == lane)
    }
    __syncwarp();

    // Own-head rows in registers
    float ph0[8], ph1[8];
    #pragma unroll
    for (int d = 0; d < 8; d++) {
        ph0[d] = sproj[warp][lane * 8 + d];
        ph1[d] = sproj[warp][(lane + 32) * 8 + d];
    }

    float acc0[8] = {0,0,0,0,0,0,0,0};
    float acc1[8] = {0,0,0,0,0,0,0,0};
    float l0 = 0.f, l1 = 0.f;
    const float inv_sqrt8 = 0.35355339059327373f;

    #pragma unroll 2
    for (int g = 0; g < 64; g++) {
        // Uniform address -> smem broadcast
        float4 pa = *(const float4*)&sproj[warp][g * 8];
        float4 pb = *(const float4*)&sproj[warp][g * 8 + 4];
        float pg[8] = {pa.x, pa.y, pa.z, pa.w, pb.x, pb.y, pb.z, pb.w};

        float s0 = 0.f, s1 = 0.f;
        #pragma unroll
        for (int d = 0; d < 8; d++) {
            s0 = fmaf(ph0[d], pg[d], s0);
            s1 = fmaf(ph1[d], pg[d], s1);
        }
        // |s*inv| <= sqrt(8): exp is safe without max subtraction
        float p0 = __expf(s0 * inv_sqrt8);
        float p1 = __expf(s1 * inv_sqrt8);
        l0 += p0; l1 += p1;
        #pragma unroll
        for (int d = 0; d < 8; d++) {
            acc0[d] = fmaf(p0, pg[d], acc0[d]);
            acc1[d] = fmaf(p1, pg[d], acc1[d]);
        }
    }

    const float r0 = __frcp_rn(l0), r1 = __frcp_rn(l1);

    // Permuted scatter: token = b*2048 + s
    const int b = token >> 11;
    const int s = token & 2047;
    const size_t base = ((size_t)b * 2048 + (s >> 6)) * EDIM + (size_t)(s & 63) * 8;
    const int h0 = lane, h1 = lane + 32;

    __half2 v[4];
    #pragma unroll
    for (int k = 0; k < 4; k++)
        v[k] = __floats2half2_rn(acc0[2 * k] * r0, acc0[2 * k + 1] * r0);
    *(uint4*)&g_y[base + (size_t)h0 * 32 * EDIM] = *(uint4*)v;
    #pragma unroll
    for (int k = 0; k < 4; k++)
        v[k] = __floats2half2_rn(acc1[2 * k] * r1, acc1[2 * k + 1] * r1);
    *(uint4*)&g_y[base + (size_t)h1 * 32 * EDIM] = *(uint4*)v;
}

// ---------------------------------------------------------------------------
// K3: out = y @ W^T + bias.  M=16384, N=512, K=512.
// fp16 wmma (16x16x16), fp32 accumulate, bias fused. BM=128 BN=64 BK=64,
// 8 warps arranged 4x2, each computing a 32x32 warp tile (2x2 fragments).
// ---------------------------------------------------------------------------
__global__ __launch_bounds__(256) void gemm_kernel(const float* __restrict__ bias,
                                                   float* __restrict__ out) {
    using namespace nvcuda;
    // Shared scratch reused: input staging (27.6 KB) then fp32 output staging (34.8 KB)
    __shared__ __align__(16) char smem_raw[128 * 68 * sizeof(float)];
    __half (*As)[72] = reinterpret_cast<__half(*)[72]>(smem_raw);                   // 128x72
    __half (*Bs)[72] = reinterpret_cast<__half(*)[72]>(smem_raw + 128 * 72 * 2);    // 64x72
    float  (*Cs)[68] = reinterpret_cast<float (*)[68]>(smem_raw);                   // 128x68

    const int tid  = threadIdx.x;
    const int warp = tid >> 5;
    const int wm   = warp >> 1;     // 0..3
    const int wn   = warp & 1;      // 0..1
    const int blockM = blockIdx.x * 128;
    const int blockN = blockIdx.y * 64;

    wmma::fragment<wmma::accumulator, 16, 16, 16, float> fc[2][2];
    #pragma unroll
    for (int i = 0; i < 2; i++)
        #pragma unroll
        for (int j = 0; j < 2; j++)
            wmma::fill_fragment(fc[i][j], 0.0f);

    for (int kt = 0; kt < 512; kt += 64) {
        __syncthreads();   // previous iteration's mma reads done (frags in regs, but loads below overwrite)
        // A tile: 128x64 halfs, 16B per thread x4
        #pragma unroll
        for (int i = 0; i < 4; i++) {
            int idx = tid + i * 256;            // 0..1023
            int row = idx >> 3;
            int col = (idx & 7) * 8;
            *(uint4*)&As[row][col] =
                *(const uint4*)&g_y[(size_t)(blockM + row) * 512 + kt + col];
        }
        // B tile: 64x64 halfs (W rows are output features; K contiguous)
        #pragma unroll
        for (int i = 0; i < 2; i++) {
            int idx = tid + i * 256;            // 0..511
            int row = idx >> 3;
            int col = (idx & 7) * 8;
            *(uint4*)&Bs[row][col] =
                *(const uint4*)&g_W[(size_t)(blockN + row) * 512 + kt + col];
        }
        __syncthreads();

        #pragma unroll
        for (int kk = 0; kk < 64; kk += 16) {
            wmma::fragment<wmma::matrix_a, 16, 16, 16, __half, wmma::row_major> fa[2];
            wmma::fragment<wmma::matrix_b, 16, 16, 16, __half, wmma::col_major> fb[2];
            wmma::load_matrix_sync(fa[0], &As[wm * 32][kk], 72);
            wmma::load_matrix_sync(fa[1], &As[wm * 32 + 16][kk], 72);
            // col_major view: (k,n) at Bs[n][k]; column stride = 72
            wmma::load_matrix_sync(fb[0], &Bs[wn * 32][kk], 72);
            wmma::load_matrix_sync(fb[1], &Bs[wn * 32 + 16][kk], 72);
            #pragma unroll
            for (int i = 0; i < 2; i++)
                #pragma unroll
                for (int j = 0; j < 2; j++)
                    wmma::mma_sync(fc[i][j], fa[i], fb[j], fc[i][j]);
        }
    }

    __syncthreads();
    #pragma unroll
    for (int i = 0; i < 2; i++)
        #pragma unroll
        for (int j = 0; j < 2; j++)
            wmma::store_matrix_sync(&Cs[wm * 32 + i * 16][wn * 32 + j * 16],
                                    fc[i][j], 68, wmma::mem_row_major);
    __syncthreads();

    #pragma unroll
    for (int i = 0; i < 32; i++) {
        int idx = tid + i * 256;                // 0..8191
        int row = idx >> 6;
        int col = idx & 63;
        out[(size_t)(blockM + row) * 512 + blockN + col] =
            Cs[row][col] + __ldg(&bias[blockN + col]);
    }
}

// ---------------------------------------------------------------------------
extern "C" void kernel_launch(void* const* d_in, const int* in_sizes, int n_in,
                              void* d_out, int out_size) {
    const float* x     = (const float*)d_in[0];
    const float* theta = (const float*)d_in[1];
    const float* W     = (const float*)d_in[2];
    const float* bias  = (const float*)d_in[3];
    float* out = (float*)d_out;

    convert_w_kernel<<<1024, 256>>>(W);
    attn_kernel<<<TOKENS / 8, 256>>>(x, theta);
    gemm_kernel<<<dim3(16384 / 128, 512 / 64), 256>>>(bias, out);
}

// round 2
// speedup vs baseline: 1.0633x; 1.0633x over previous
#include <cuda_runtime.h>
#include <cuda_fp16.h>
#include <mma.h>

#define TOKENS (8*2048)
#define EDIM 512

// Scratch: permuted attention output in fp16, W in fp16.
__device__ __half g_y[(size_t)TOKENS * EDIM];   // 16 MB
__device__ __half g_W[EDIM * EDIM];             // 512 KB

// ---- packed f32x2 helpers (sm_100+) --------------------------------------
typedef unsigned long long u64;

__device__ __forceinline__ u64 pk2(float a, float b) {
    u64 r; asm("mov.b64 %0, {%1, %2};" : "=l"(r) : "f"(a), "f"(b)); return r;
}
__device__ __forceinline__ float2 upk2(u64 a) {
    float2 f; asm("mov.b64 {%0, %1}, %2;" : "=f"(f.x), "=f"(f.y) : "l"(a)); return f;
}
__device__ __forceinline__ u64 ffma2(u64 a, u64 b, u64 c) {
    u64 d; asm("fma.rn.f32x2 %0, %1, %2, %3;" : "=l"(d) : "l"(a), "l"(b), "l"(c)); return d;
}
__device__ __forceinline__ float ex2(float x) {
    float r; asm("ex2.approx.f32 %0, %1;" : "=f"(r) : "f"(x)); return r;
}

// ---------------------------------------------------------------------------
// K1: per-token quantum attention (one warp per token) + fused W fp16 convert.
// proj[64][8] in smem; streaming softmax (|score| <= sqrt(8), no max needed).
// Lane owns heads (lane) and (lane+32); math in packed f32x2.
// Epilogue scatters into torch-permuted layout:
//   y[b, h*32 + s/64, (s%64)*8 + d] = attn[b,s,h,d]
// ---------------------------------------------------------------------------
__global__ __launch_bounds__(256) void attn_kernel(const float* __restrict__ x,
                                                   const float* __restrict__ theta,
                                                   const float* __restrict__ W) {
    // first 128 blocks also convert W (runs in parallel, hidden under attn)
    if (blockIdx.x < 128) {
        int t = blockIdx.x * 256 + threadIdx.x;      // 0..32767, 8 elems each
        float4 aq = *(const float4*)&W[(size_t)t * 8];
        float4 bq = *(const float4*)&W[(size_t)t * 8 + 4];
        __half2 h[4] = {__floats2half2_rn(aq.x, aq.y), __floats2half2_rn(aq.z, aq.w),
                        __floats2half2_rn(bq.x, bq.y), __floats2half2_rn(bq.z, bq.w)};
        *(uint4*)&g_W[(size_t)t * 8] = *(uint4*)h;
    }

    __shared__ float sproj[8][512];
    const int warp = threadIdx.x >> 5;
    const int lane = threadIdx.x & 31;
    const int token = blockIdx.x * 8 + warp;          // [0, 16384)
    const float* xt = x + (size_t)token * EDIM;

    // idx = lane + 32*i  ->  idx & 7 == lane & 7 (one theta per lane)
    const float tv = __ldg(&theta[lane & 7]);
    #pragma unroll
    for (int i = 0; i < 16; i++) {
        int idx = lane + 32 * i;
        sproj[warp][idx] = __cosf(xt[idx] + tv);      // bank == lane, conflict-free
    }
    __syncwarp();

    // Own-head rows, packed as f32 pairs over d
    float4 c0 = *(const float4*)&sproj[warp][lane * 8];
    float4 c1 = *(const float4*)&sproj[warp][lane * 8 + 4];
    float4 c2 = *(const float4*)&sproj[warp][(lane + 32) * 8];
    float4 c3 = *(const float4*)&sproj[warp][(lane + 32) * 8 + 4];
    u64 ph0[4] = {pk2(c0.x, c0.y), pk2(c0.z, c0.w), pk2(c1.x, c1.y), pk2(c1.z, c1.w)};
    u64 ph1[4] = {pk2(c2.x, c2.y), pk2(c2.z, c2.w), pk2(c3.x, c3.y), pk2(c3.z, c3.w)};

    u64 acc0[4] = {0, 0, 0, 0};                       // bits of {0.f,0.f}
    u64 acc1[4] = {0, 0, 0, 0};
    float l0 = 0.f, l1 = 0.f;
    const float C2 = 0.51006973f;                     // log2(e)/sqrt(8)

    #pragma unroll 4
    for (int g = 0; g < 64; g++) {
        float4 pa = *(const float4*)&sproj[warp][g * 8];       // broadcast
        float4 pb = *(const float4*)&sproj[warp][g * 8 + 4];
        u64 pg[4] = {pk2(pa.x, pa.y), pk2(pa.z, pa.w), pk2(pb.x, pb.y), pk2(pb.z, pb.w)};

        u64 t0 = ffma2(ph0[0], pg[0], 0ull);
        u64 t1 = ffma2(ph1[0], pg[0], 0ull);
        #pragma unroll
        for (int k = 1; k < 4; k++) {
            t0 = ffma2(ph0[k], pg[k], t0);
            t1 = ffma2(ph1[k], pg[k], t1);
        }
        float2 f0 = upk2(t0), f1 = upk2(t1);
        float p0 = ex2((f0.x + f0.y) * C2);            // exp(score/sqrt(8))
        float p1 = ex2((f1.x + f1.y) * C2);
        l0 += p0; l1 += p1;
        u64 p0p = pk2(p0, p0), p1p = pk2(p1, p1);
        #pragma unroll
        for (int k = 0; k < 4; k++) {
            acc0[k] = ffma2(p0p, pg[k], acc0[k]);
            acc1[k] = ffma2(p1p, pg[k], acc1[k]);
        }
    }

    const float r0 = __frcp_rn(l0), r1 = __frcp_rn(l1);

    // Permuted scatter: token = b*2048 + s
    const int b = token >> 11;
    const int s = token & 2047;
    const size_t base = ((size_t)b * 2048 + (s >> 6)) * EDIM + (size_t)(s & 63) * 8;

    __half2 v[4];
    #pragma unroll
    for (int k = 0; k < 4; k++) {
        float2 a = upk2(acc0[k]);
        v[k] = __floats2half2_rn(a.x * r0, a.y * r0);
    }
    *(uint4*)&g_y[base + (size_t)lane * 32 * EDIM] = *(uint4*)v;
    #pragma unroll
    for (int k = 0; k < 4; k++) {
        float2 a = upk2(acc1[k]);
        v[k] = __floats2half2_rn(a.x * r1, a.y * r1);
    }
    *(uint4*)&g_y[base + (size_t)(lane + 32) * 32 * EDIM] = *(uint4*)v;
}

// ---------------------------------------------------------------------------
// K2: out = y @ W^T + bias.  M=16384, N=512, K=512.
// BM=128 BN=128 BK=64, 8 warps (2x4), warp tile 64x32 (4x2 frags).
// Bias preloaded into accumulator frags; results stored straight to global.
// ---------------------------------------------------------------------------
__global__ __launch_bounds__(256) void gemm_kernel(const float* __restrict__ bias,
                                                   float* __restrict__ out) {
    using namespace nvcuda;
    __shared__ __align__(16) __half As[128][72];
    __shared__ __align__(16) __half Bs[128][72];

    const int tid  = threadIdx.x;
    const int warp = tid >> 5;
    const int wm   = warp >> 2;     // 0..1  (64 rows each)
    const int wn   = warp & 3;      // 0..3  (32 cols each)
    const int blockM = blockIdx.x * 128;
    const int blockN = blockIdx.y * 128;

    // --- bias -> accumulator fragments (via 16 replicated rows in smem) ----
    float (*bt)[128] = reinterpret_cast<float(*)[128]>(&As[0][0]);   // 8 KB overlay
    #pragma unroll
    for (int i = 0; i < 8; i++) {
        int idx = tid + i * 256;                 // 0..2047
        bt[idx >> 7][idx & 127] = __ldg(&bias[blockN + (idx & 127)]);
    }
    __syncthreads();

    wmma::fragment<wmma::accumulator, 16, 16, 16, float> fc[4][2];
    #pragma unroll
    for (int i = 0; i < 4; i++)
        #pragma unroll
        for (int j = 0; j < 2; j++)
            wmma::load_matrix_sync(fc[i][j], &bt[0][wn * 32 + j * 16], 128,
                                   wmma::mem_row_major);
    __syncthreads();

    // --- main loop ----------------------------------------------------------
    for (int kt = 0; kt < 512; kt += 64) {
        #pragma unroll
        for (int i = 0; i < 4; i++) {
            int idx = tid + i * 256;             // 0..1023
            int row = idx >> 3;
            int col = (idx & 7) * 8;
            *(uint4*)&As[row][col] =
                *(const uint4*)&g_y[(size_t)(blockM + row) * 512 + kt + col];
            *(uint4*)&Bs[row][col] =
                *(const uint4*)&g_W[(size_t)(blockN + row) * 512 + kt + col];
        }
        __syncthreads();

        #pragma unroll
        for (int kk = 0; kk < 64; kk += 16) {
            wmma::fragment<wmma::matrix_a, 16, 16, 16, __half, wmma::row_major> fa[4];
            wmma::fragment<wmma::matrix_b, 16, 16, 16, __half, wmma::col_major> fb[2];
            #pragma unroll
            for (int i = 0; i < 4; i++)
                wmma::load_matrix_sync(fa[i], &As[wm * 64 + i * 16][kk], 72);
            #pragma unroll
            for (int j = 0; j < 2; j++)
                wmma::load_matrix_sync(fb[j], &Bs[wn * 32 + j * 16][kk], 72);
            #pragma unroll
            for (int i = 0; i < 4; i++)
                #pragma unroll
                for (int j = 0; j < 2; j++)
                    wmma::mma_sync(fc[i][j], fa[i], fb[j], fc[i][j]);
        }
        __syncthreads();
    }

    // --- epilogue: straight to global ---------------------------------------
    #pragma unroll
    for (int i = 0; i < 4; i++)
        #pragma unroll
        for (int j = 0; j < 2; j++)
            wmma::store_matrix_sync(
                &out[(size_t)(blockM + wm * 64 + i * 16) * 512 + blockN + wn * 32 + j * 16],
                fc[i][j], 512, wmma::mem_row_major);
}

// ---------------------------------------------------------------------------
extern "C" void kernel_launch(void* const* d_in, const int* in_sizes, int n_in,
                              void* d_out, int out_size) {
    const float* x     = (const float*)d_in[0];
    const float* theta = (const float*)d_in[1];
    const float* W     = (const float*)d_in[2];
    const float* bias  = (const float*)d_in[3];
    float* out = (float*)d_out;

    attn_kernel<<<TOKENS / 8, 256>>>(x, theta, W);
    gemm_kernel<<<dim3(16384 / 128, 512 / 128), 256>>>(bias, out);
}

// round 4
// speedup vs baseline: 1.6661x; 1.5669x over previous
#include <cuda_runtime.h>
#include <cuda_fp16.h>
#include <mma.h>
#include <cstdint>

#define TOKENS (8*2048)
#define EDIM 512

// Scratch: permuted attention output in fp16, W in fp16.
__device__ __half g_y[(size_t)TOKENS * EDIM];   // 16 MB
__device__ __half g_W[EDIM * EDIM];             // 512 KB

// ============================ helpers ======================================
__device__ __forceinline__ float ex2(float x) {
    float r; asm("ex2.approx.f32 %0, %1;" : "=f"(r) : "f"(x)); return r;
}
__device__ __forceinline__ uint32_t f22h2(float a, float b) {
    __half2 h = __floats2half2_rn(a, b);
    return *(uint32_t*)&h;
}
// D += A(m16k8,f16) * B(k8n8,f16), f32 accum (in place on c[4])
__device__ __forceinline__ void mma_16n8k8(float* c, uint32_t a0, uint32_t a1, uint32_t b0) {
    asm volatile(
        "mma.sync.aligned.m16n8k8.row.col.f32.f16.f16.f32 "
        "{%0,%1,%2,%3}, {%4,%5}, {%6}, {%0,%1,%2,%3};"
        : "+f"(c[0]), "+f"(c[1]), "+f"(c[2]), "+f"(c[3])
        : "r"(a0), "r"(a1), "r"(b0));
}

// ---------------------------------------------------------------------------
// K1: per-token quantum attention, tensor-core version. One warp per token.
//   P = cos(x+theta) (64 heads x 8 dims), S = P P^T * C2 (C2 folds 1/sqrt(8)
//   and log2e), p = 2^S, O = p*P, out = O / rowsum(p), scattered into the
//   torch-permuted layout. S-mma C-fragments feed O-mma A-fragments directly
//   (identical lane layouts). First 128 blocks also convert W to fp16.
// ---------------------------------------------------------------------------
__global__ __launch_bounds__(256) void attn_kernel(const float* __restrict__ x,
                                                   const float* __restrict__ theta,
                                                   const float* __restrict__ W) {
    if (blockIdx.x < 128) {   // hidden W fp16 convert
        int t = blockIdx.x * 256 + threadIdx.x;
        float4 aq = *(const float4*)&W[(size_t)t * 8];
        float4 bq = *(const float4*)&W[(size_t)t * 8 + 4];
        __half2 h[4] = {__floats2half2_rn(aq.x, aq.y), __floats2half2_rn(aq.z, aq.w),
                        __floats2half2_rn(bq.x, bq.y), __floats2half2_rn(bq.z, bq.w)};
        *(uint4*)&g_W[(size_t)t * 8] = *(uint4*)h;
    }

    __shared__ float sproj[8][512];        // [warp][h*8+d]
    __shared__ float sprojT[8][8][68];     // [warp][d][h], padded pitch 68

    const int warp = threadIdx.x >> 5;
    const int lane = threadIdx.x & 31;
    const int token = blockIdx.x * 8 + warp;
    const float* xt = x + (size_t)token * EDIM;

    const float tv = __ldg(&theta[lane & 7]);
    #pragma unroll
    for (int i = 0; i < 16; i++) {
        int idx = lane + 32 * i;
        float c = __cosf(xt[idx] + tv);
        sproj[warp][idx] = c;
        sprojT[warp][idx & 7][idx >> 3] = c;
    }
    __syncwarp();

    const int q  = lane >> 2;        // fragment groupID (row-in-tile)
    const int r2 = (lane & 3) * 2;   // fragment pair column
    const float C2 = 0.51006973f;    // log2(e)/sqrt(8)

    // A fragments of P (prescaled): tile mi covers heads 16mi..16mi+15
    uint32_t aA[4][2];
    #pragma unroll
    for (int mi = 0; mi < 4; mi++) {
        float2 lo = *(const float2*)&sproj[warp][(16 * mi + q) * 8 + r2];
        float2 hi = *(const float2*)&sproj[warp][(16 * mi + q + 8) * 8 + r2];
        aA[mi][0] = f22h2(lo.x * C2, lo.y * C2);
        aA[mi][1] = f22h2(hi.x * C2, hi.y * C2);
    }

    float o[4][4];
    float lsl[4], lsh[4];
    #pragma unroll
    for (int mi = 0; mi < 4; mi++) {
        o[mi][0] = o[mi][1] = o[mi][2] = o[mi][3] = 0.f;
        lsl[mi] = lsh[mi] = 0.f;
    }

    #pragma unroll
    for (int nj = 0; nj < 8; nj++) {
        // B for S-mma: (k=d, n=g=8nj+q) -> P[g][d], contiguous float2
        float2 bs = *(const float2*)&sproj[warp][(8 * nj + q) * 8 + r2];
        uint32_t bS = f22h2(bs.x, bs.y);
        // B for O-mma: (k=g_local=r2+{0,1}, n=d=q) -> P[8nj+r2+{0,1}][q] = sprojT[q][g]
        float2 bo = *(const float2*)&sprojT[warp][q][8 * nj + r2];
        uint32_t bO = f22h2(bo.x, bo.y);

        #pragma unroll
        for (int mi = 0; mi < 4; mi++) {
            float c[4] = {0.f, 0.f, 0.f, 0.f};
            mma_16n8k8(c, aA[mi][0], aA[mi][1], bS);
            float p0 = ex2(c[0]), p1 = ex2(c[1]), p2 = ex2(c[2]), p3 = ex2(c[3]);
            lsl[mi] += p0 + p1;
            lsh[mi] += p2 + p3;
            // C layout == A layout: rows h=16mi+q(+8), cols g_local=r2+{0,1}
            mma_16n8k8(o[mi], f22h2(p0, p1), f22h2(p2, p3), bO);
        }
    }

    // Row sums: reduce across the quad (lanes sharing groupID)
    #pragma unroll
    for (int mi = 0; mi < 4; mi++) {
        lsl[mi] += __shfl_xor_sync(0xffffffffu, lsl[mi], 1);
        lsl[mi] += __shfl_xor_sync(0xffffffffu, lsl[mi], 2);
        lsh[mi] += __shfl_xor_sync(0xffffffffu, lsh[mi], 1);
        lsh[mi] += __shfl_xor_sync(0xffffffffu, lsh[mi], 2);
    }

    // Scatter: y[b, h*32 + s/64, (s%64)*8 + d]
    const int b = token >> 11;
    const int s = token & 2047;
    const size_t base = ((size_t)b * 2048 + (s >> 6)) * EDIM + (size_t)(s & 63) * 8;

    #pragma unroll
    for (int mi = 0; mi < 4; mi++) {
        float rl = __frcp_rn(lsl[mi]);
        float rh = __frcp_rn(lsh[mi]);
        int h0 = 16 * mi + q;
        __half2 v0 = __floats2half2_rn(o[mi][0] * rl, o[mi][1] * rl);
        *(__half2*)&g_y[base + (size_t)h0 * 32 * EDIM + r2] = v0;
        __half2 v1 = __floats2half2_rn(o[mi][2] * rh, o[mi][3] * rh);
        *(__half2*)&g_y[base + (size_t)(h0 + 8) * 32 * EDIM + r2] = v1;
    }
}

// ---------------------------------------------------------------------------
// K2: out = y @ W^T + bias.  M=16384, N=512, K=512.  (unchanged from R2)
// BM=128 BN=128 BK=64, 8 warps (2x4), warp tile 64x32 (4x2 frags).
// ---------------------------------------------------------------------------
__global__ __launch_bounds__(256) void gemm_kernel(const float* __restrict__ bias,
                                                   float* __restrict__ out) {
    using namespace nvcuda;
    __shared__ __align__(16) __half As[128][72];
    __shared__ __align__(16) __half Bs[128][72];

    const int tid  = threadIdx.x;
    const int warp = tid >> 5;
    const int wm   = warp >> 2;
    const int wn   = warp & 3;
    const int blockM = blockIdx.x * 128;
    const int blockN = blockIdx.y * 128;

    float (*bt)[128] = reinterpret_cast<float(*)[128]>(&As[0][0]);
    #pragma unroll
    for (int i = 0; i < 8; i++) {
        int idx = tid + i * 256;
        bt[idx >> 7][idx & 127] = __ldg(&bias[blockN + (idx & 127)]);
    }
    __syncthreads();

    wmma::fragment<wmma::accumulator, 16, 16, 16, float> fc[4][2];
    #pragma unroll
    for (int i = 0; i < 4; i++)
        #pragma unroll
        for (int j = 0; j < 2; j++)
            wmma::load_matrix_sync(fc[i][j], &bt[0][wn * 32 + j * 16], 128,
                                   wmma::mem_row_major);
    __syncthreads();

    for (int kt = 0; kt < 512; kt += 64) {
        #pragma unroll
        for (int i = 0; i < 4; i++) {
            int idx = tid + i * 256;
            int row = idx >> 3;
            int col = (idx & 7) * 8;
            *(uint4*)&As[row][col] =
                *(const uint4*)&g_y[(size_t)(blockM + row) * 512 + kt + col];
            *(uint4*)&Bs[row][col] =
                *(const uint4*)&g_W[(size_t)(blockN + row) * 512 + kt + col];
        }
        __syncthreads();

        #pragma unroll
        for (int kk = 0; kk < 64; kk += 16) {
            wmma::fragment<wmma::matrix_a, 16, 16, 16, __half, wmma::row_major> fa[4];
            wmma::fragment<wmma::matrix_b, 16, 16, 16, __half, wmma::col_major> fb[2];
            #pragma unroll
            for (int i = 0; i < 4; i++)
                wmma::load_matrix_sync(fa[i], &As[wm * 64 + i * 16][kk], 72);
            #pragma unroll
            for (int j = 0; j < 2; j++)
                wmma::load_matrix_sync(fb[j], &Bs[wn * 32 + j * 16][kk], 72);
            #pragma unroll
            for (int i = 0; i < 4; i++)
                #pragma unroll
                for (int j = 0; j < 2; j++)
                    wmma::mma_sync(fc[i][j], fa[i], fb[j], fc[i][j]);
        }
        __syncthreads();
    }

    #pragma unroll
    for (int i = 0; i < 4; i++)
        #pragma unroll
        for (int j = 0; j < 2; j++)
            wmma::store_matrix_sync(
                &out[(size_t)(blockM + wm * 64 + i * 16) * 512 + blockN + wn * 32 + j * 16],
                fc[i][j], 512, wmma::mem_row_major);
}

// ---------------------------------------------------------------------------
extern "C" void kernel_launch(void* const* d_in, const int* in_sizes, int n_in,
                              void* d_out, int out_size) {
    const float* x     = (const float*)d_in[0];
    const float* theta = (const float*)d_in[1];
    const float* W     = (const float*)d_in[2];
    const float* bias  = (const float*)d_in[3];
    float* out = (float*)d_out;

    attn_kernel<<<TOKENS / 8, 256>>>(x, theta, W);
    gemm_kernel<<<dim3(16384 / 128, 512 / 128), 256>>>(bias, out);
}

// round 6
// speedup vs baseline: 1.8072x; 1.0846x over previous
#include <cuda_runtime.h>
#include <cuda_fp16.h>
#include <cstdint>

#define TOKENS (8*2048)
#define EDIM 512

// Scratch: permuted attention output in fp16, W in fp16.
__device__ __half g_y[(size_t)TOKENS * EDIM];   // 16 MB
__device__ __half g_W[EDIM * EDIM];             // 512 KB

// ============================ helpers ======================================
__device__ __forceinline__ float ex2(float x) {
    float r; asm("ex2.approx.f32 %0, %1;" : "=f"(r) : "f"(x)); return r;
}
__device__ __forceinline__ uint32_t f22h2(float a, float b) {
    __half2 h = __floats2half2_rn(a, b);
    return *(uint32_t*)&h;
}
__device__ __forceinline__ uint32_t smem_u32(const void* p) {
    uint32_t a;
    asm("{ .reg .u64 t; cvta.to.shared.u64 t, %1; cvt.u32.u64 %0, t; }" : "=r"(a) : "l"(p));
    return a;
}
__device__ __forceinline__ void mma_16n8k8(float* c, uint32_t a0, uint32_t a1, uint32_t b0) {
    asm volatile(
        "mma.sync.aligned.m16n8k8.row.col.f32.f16.f16.f32 "
        "{%0,%1,%2,%3}, {%4,%5}, {%6}, {%0,%1,%2,%3};"
        : "+f"(c[0]), "+f"(c[1]), "+f"(c[2]), "+f"(c[3])
        : "r"(a0), "r"(a1), "r"(b0));
}
__device__ __forceinline__ void mma_16n8k16(float* c, const uint32_t* a,
                                            uint32_t b0, uint32_t b1) {
    asm volatile(
        "mma.sync.aligned.m16n8k16.row.col.f32.f16.f16.f32 "
        "{%0,%1,%2,%3}, {%4,%5,%6,%7}, {%8,%9}, {%0,%1,%2,%3};"
        : "+f"(c[0]), "+f"(c[1]), "+f"(c[2]), "+f"(c[3])
        : "r"(a[0]), "r"(a[1]), "r"(a[2]), "r"(a[3]), "r"(b0), "r"(b1));
}
__device__ __forceinline__ void ldsm_x4(uint32_t* r, uint32_t addr) {
    asm volatile("ldmatrix.sync.aligned.m8n8.x4.shared.b16 {%0,%1,%2,%3}, [%4];"
        : "=r"(r[0]), "=r"(r[1]), "=r"(r[2]), "=r"(r[3]) : "r"(addr));
}
__device__ __forceinline__ void cp16(uint32_t saddr, const void* gptr) {
    asm volatile("cp.async.cg.shared.global [%0], [%1], 16;" :: "r"(saddr), "l"(gptr));
}
#define CP_COMMIT()  asm volatile("cp.async.commit_group;" ::: "memory")
#define CP_WAIT(n)   asm volatile("cp.async.wait_group %0;" :: "n"(n) : "memory")
#define SW128(o) ((o) ^ (((o) >> 3) & 0x70))

// ---------------------------------------------------------------------------
// K1: per-token quantum attention, tensor-core version (unchanged from R4).
// ---------------------------------------------------------------------------
__global__ __launch_bounds__(256) void attn_kernel(const float* __restrict__ x,
                                                   const float* __restrict__ theta,
                                                   const float* __restrict__ W) {
    if (blockIdx.x < 128) {   // hidden W fp16 convert
        int t = blockIdx.x * 256 + threadIdx.x;
        float4 aq = *(const float4*)&W[(size_t)t * 8];
        float4 bq = *(const float4*)&W[(size_t)t * 8 + 4];
        __half2 h[4] = {__floats2half2_rn(aq.x, aq.y), __floats2half2_rn(aq.z, aq.w),
                        __floats2half2_rn(bq.x, bq.y), __floats2half2_rn(bq.z, bq.w)};
        *(uint4*)&g_W[(size_t)t * 8] = *(uint4*)h;
    }

    __shared__ float sproj[8][512];        // [warp][h*8+d]
    __shared__ float sprojT[8][8][68];     // [warp][d][h], padded pitch 68

    const int warp = threadIdx.x >> 5;
    const int lane = threadIdx.x & 31;
    const int token = blockIdx.x * 8 + warp;
    const float* xt = x + (size_t)token * EDIM;

    const float tv = __ldg(&theta[lane & 7]);
    #pragma unroll
    for (int i = 0; i < 16; i++) {
        int idx = lane + 32 * i;
        float c = __cosf(xt[idx] + tv);
        sproj[warp][idx] = c;
        sprojT[warp][idx & 7][idx >> 3] = c;
    }
    __syncwarp();

    const int q  = lane >> 2;
    const int r2 = (lane & 3) * 2;
    const float C2 = 0.51006973f;    // log2(e)/sqrt(8)

    uint32_t aA[4][2];
    #pragma unroll
    for (int mi = 0; mi < 4; mi++) {
        float2 lo = *(const float2*)&sproj[warp][(16 * mi + q) * 8 + r2];
        float2 hi = *(const float2*)&sproj[warp][(16 * mi + q + 8) * 8 + r2];
        aA[mi][0] = f22h2(lo.x * C2, lo.y * C2);
        aA[mi][1] = f22h2(hi.x * C2, hi.y * C2);
    }

    float o[4][4];
    float lsl[4], lsh[4];
    #pragma unroll
    for (int mi = 0; mi < 4; mi++) {
        o[mi][0] = o[mi][1] = o[mi][2] = o[mi][3] = 0.f;
        lsl[mi] = lsh[mi] = 0.f;
    }

    #pragma unroll
    for (int nj = 0; nj < 8; nj++) {
        float2 bs = *(const float2*)&sproj[warp][(8 * nj + q) * 8 + r2];
        uint32_t bS = f22h2(bs.x, bs.y);
        float2 bo = *(const float2*)&sprojT[warp][q][8 * nj + r2];
        uint32_t bO = f22h2(bo.x, bo.y);

        #pragma unroll
        for (int mi = 0; mi < 4; mi++) {
            float c[4] = {0.f, 0.f, 0.f, 0.f};
            mma_16n8k8(c, aA[mi][0], aA[mi][1], bS);
            float p0 = ex2(c[0]), p1 = ex2(c[1]), p2 = ex2(c[2]), p3 = ex2(c[3]);
            lsl[mi] += p0 + p1;
            lsh[mi] += p2 + p3;
            mma_16n8k8(o[mi], f22h2(p0, p1), f22h2(p2, p3), bO);
        }
    }

    #pragma unroll
    for (int mi = 0; mi < 4; mi++) {
        lsl[mi] += __shfl_xor_sync(0xffffffffu, lsl[mi], 1);
        lsl[mi] += __shfl_xor_sync(0xffffffffu, lsl[mi], 2);
        lsh[mi] += __shfl_xor_sync(0xffffffffu, lsh[mi], 1);
        lsh[mi] += __shfl_xor_sync(0xffffffffu, lsh[mi], 2);
    }

    const int b = token >> 11;
    const int s = token & 2047;
    const size_t base = ((size_t)b * 2048 + (s >> 6)) * EDIM + (size_t)(s & 63) * 8;

    #pragma unroll
    for (int mi = 0; mi < 4; mi++) {
        float rl = __frcp_rn(lsl[mi]);
        float rh = __frcp_rn(lsh[mi]);
        int h0 = 16 * mi + q;
        __half2 v0 = __floats2half2_rn(o[mi][0] * rl, o[mi][1] * rl);
        *(__half2*)&g_y[base + (size_t)h0 * 32 * EDIM + r2] = v0;
        __half2 v1 = __floats2half2_rn(o[mi][2] * rh, o[mi][3] * rh);
        *(__half2*)&g_y[base + (size_t)(h0 + 8) * 32 * EDIM + r2] = v1;
    }
}

// ---------------------------------------------------------------------------
// K2: out = y @ W^T + bias.  M=16384, N=512, K=512.
// mma.sync.m16n8k16 + ldmatrix (B NON-trans: W is [n][k], k contiguous)
// + SW128 swizzle + cp.async 2-stage pipeline.
// BM=128 BN=128 BK=64; 8 warps (2x4), warp tile 64x32.
// ---------------------------------------------------------------------------
#define STAGE_BYTES 32768            // 16KB A + 16KB B per stage
#define GEMM_SMEM   65536

__global__ __launch_bounds__(256) void gemm_kernel(const float* __restrict__ bias,
                                                   float* __restrict__ out) {
    extern __shared__ __align__(1024) char smem[];
    const uint32_t sb = smem_u32(smem);
    const int tid  = threadIdx.x;
    const int warp = tid >> 5;
    const int lane = tid & 31;
    const int wm   = warp >> 2;      // 0..1
    const int wn   = warp & 3;       // 0..3
    const int blockM = blockIdx.x * 128;
    const int blockN = blockIdx.y * 128;

    const int lrow = tid >> 3;            // 0..31
    const int lcb  = (tid & 7) * 16;      // byte col in 128B row

    auto load_stage = [&](int s) {
        const int kt = s * 64;
        const uint32_t base = sb + (s & 1) * STAGE_BYTES;
        #pragma unroll
        for (int i = 0; i < 4; i++) {
            int row = lrow + i * 32;
            uint32_t o = SW128(row * 128 + lcb);
            cp16(base + o, &g_y[(size_t)(blockM + row) * 512 + kt + (lcb >> 1)]);
            cp16(base + 16384 + o, &g_W[(size_t)(blockN + row) * 512 + kt + (lcb >> 1)]);
        }
        CP_COMMIT();
    };

    float c[4][4][4];
    #pragma unroll
    for (int mi = 0; mi < 4; mi++)
        #pragma unroll
        for (int nj = 0; nj < 4; nj++)
            c[mi][nj][0] = c[mi][nj][1] = c[mi][nj][2] = c[mi][nj][3] = 0.f;

    load_stage(0);

    const int t  = lane & 15;        // row within 16-row ldmatrix tile
    const int hh = (lane >> 4) * 16; // 16B k-half select

    #pragma unroll 1
    for (int s = 0; s < 8; s++) {
        if (s + 1 < 8) { load_stage(s + 1); CP_WAIT(1); }
        else           { CP_WAIT(0); }
        __syncthreads();

        const uint32_t abase = sb + (s & 1) * STAGE_BYTES;
        const uint32_t bbase = abase + 16384;

        #pragma unroll
        for (int ks = 0; ks < 4; ks++) {
            uint32_t ra[4][4], rb[2][4];
            #pragma unroll
            for (int mi = 0; mi < 4; mi++) {
                uint32_t o = (wm * 64 + mi * 16 + t) * 128 + ks * 32 + hh;
                ldsm_x4(ra[mi], abase + SW128(o));
            }
            #pragma unroll
            for (int g = 0; g < 2; g++) {
                uint32_t o = (wn * 32 + g * 16 + t) * 128 + ks * 32 + hh;
                ldsm_x4(rb[g], bbase + SW128(o));   // NON-trans: rows = n, k contiguous
            }
            #pragma unroll
            for (int mi = 0; mi < 4; mi++)
                #pragma unroll
                for (int nj = 0; nj < 4; nj++)
                    mma_16n8k16(c[mi][nj], ra[mi],
                                rb[nj >> 1][nj & 1], rb[nj >> 1][2 + (nj & 1)]);
        }
        __syncthreads();
    }

    // epilogue: bias + direct float2 stores
    const int q  = lane >> 2;
    const int r2 = (lane & 3) * 2;
    #pragma unroll
    for (int nj = 0; nj < 4; nj++) {
        const int col = blockN + wn * 32 + nj * 8 + r2;
        const float2 bv = *(const float2*)&bias[col];
        #pragma unroll
        for (int mi = 0; mi < 4; mi++) {
            const int row = blockM + wm * 64 + mi * 16 + q;
            float2 v0 = {c[mi][nj][0] + bv.x, c[mi][nj][1] + bv.y};
            float2 v1 = {c[mi][nj][2] + bv.x, c[mi][nj][3] + bv.y};
            *(float2*)&out[(size_t)row * 512 + col] = v0;
            *(float2*)&out[(size_t)(row + 8) * 512 + col] = v1;
        }
    }
}

// ---------------------------------------------------------------------------
extern "C" void kernel_launch(void* const* d_in, const int* in_sizes, int n_in,
                              void* d_out, int out_size) {
    const float* x     = (const float*)d_in[0];
    const float* theta = (const float*)d_in[1];
    const float* W     = (const float*)d_in[2];
    const float* bias  = (const float*)d_in[3];
    float* out = (float*)d_out;

    cudaFuncSetAttribute(gemm_kernel, cudaFuncAttributeMaxDynamicSharedMemorySize, GEMM_SMEM);
    attn_kernel<<<TOKENS / 8, 256>>>(x, theta, W);
    gemm_kernel<<<dim3(16384 / 128, 512 / 128), 256, GEMM_SMEM>>>(bias, out);
}